// round 11
// baseline (speedup 1.0000x reference)
#include <cuda_runtime.h>
#include <cstdint>

// Problem: B=16, S=4096, D=64, K=4096
#define D_DIM    64
#define K_CODES  4096
#define N_ROWS   65536
#define ROWS_CTA 64
#define THREADS  128
#define WCHUNK   128                    // codes per smem chunk
#define N_CHUNKS (K_CODES / WCHUNK)     // 32
#define N_BLOCKS (N_ROWS / ROWS_CTA)    // 1024
#define NQ_ELEMS (N_ROWS * D_DIM)
#define CAP      64
#define S_E      520192.0f              // 127 * 4096
#define EEMAX    3.8148e-6f             // max ||e||^2 = 64/4096^2 (+margin)
#define IBV_INIT (-(1 << 30))           // safe sentinel: no underflow after -idl

// smem byte offsets
#define SM_EQ    0                      // 2 x 128 x 64  = 16384 (int8 codes, swizzled)
#define SM_ZF    16384                  // 64 x 68 x 4   = 17408 (z fp32)
#define SM_ZQ    33792                  // 64 x 64       = 4096  (z int8, swizzled)
#define SM_CAND  37888                  // 64 x 64 x 4   = 16384
#define SM_CNT   54272                  // 64 x 4
#define SM_ENC   54528                  // 64 x 4 (int running-max idot)
#define SM_ZZ    54784                  // 64 x 4
#define SM_IDL   55040                  // 64 x 4 (int slack)
#define SM_LOSS  55296                  // 64 x 8
#define SM_TOTAL 55808                  // x4 CTAs = 223232 B <= 228 KB -> occ 4

__device__ uint32_t g_eq[K_CODES * 16];     // packed int8 codebook [k][16 u32]
__device__ float    g_ee[K_CODES];          // exact ||e||^2, serial fp32 chain
__device__ double   g_lossPart[N_BLOCKS];

__device__ __forceinline__ uint32_t smem_u32(const void* p) {
    return (uint32_t)__cvta_generic_to_shared(p);
}
#define CP16(dst, src) \
    asm volatile("cp.async.cg.shared.global [%0], [%1], 16;" :: "r"(dst), "l"(src))
#define CP_COMMIT() asm volatile("cp.async.commit_group;" ::: "memory")
#define CP_WAIT0()  asm volatile("cp.async.wait_group 0;" ::: "memory")
#define CP_WAIT1()  asm volatile("cp.async.wait_group 1;" ::: "memory")

__device__ __forceinline__ uint32_t pack4(const float* v, float s) {
    int a0 = __float2int_rn(v[0] * s), a1 = __float2int_rn(v[1] * s);
    int a2 = __float2int_rn(v[2] * s), a3 = __float2int_rn(v[3] * s);
    return (uint32_t)(a0 & 0xFF) | ((uint32_t)(a1 & 0xFF) << 8) |
           ((uint32_t)(a2 & 0xFF) << 16) | ((uint32_t)(a3 & 0xFF) << 24);
}

// ---------------------------------------------------------------------------
// Prep: exact ||e||^2 (serial fp32) + packed int8 codebook
// ---------------------------------------------------------------------------
__global__ void vq_prep(const float* __restrict__ emb) {
    __shared__ float tile[32][D_DIM + 1];
    const int tid = threadIdx.x;             // 256
    const int k0  = blockIdx.x * 32;

    #pragma unroll
    for (int it = 0; it < 8; ++it) {
        int i = tid + it * 256;
        int kl = i >> 6, d = i & 63;
        tile[kl][d] = __ldg(&emb[(size_t)(k0 + kl) * D_DIM + d]);
    }
    __syncthreads();

    if (tid < 32) {
        float s = 0.0f;
        #pragma unroll
        for (int d = 0; d < D_DIM; ++d) {
            float v = tile[tid][d];
            s = __fadd_rn(s, __fmul_rn(v, v));
        }
        g_ee[k0 + tid] = s;
    }
    #pragma unroll
    for (int it = 0; it < 2; ++it) {
        int i = tid + it * 256;              // 0..511
        int code = i >> 4, g = i & 15;
        g_eq[(size_t)(k0 + code) * 16 + g] = pack4(&tile[code][g * 4], S_E);
    }
}

// ---------------------------------------------------------------------------
// Screen (integer) + exact rescore
// ---------------------------------------------------------------------------
__device__ __forceinline__ void load_tile(char* smb, int buf, int chunk, int tid) {
    uint32_t eqBase = smem_u32(smb + SM_EQ + buf * 8192);
    #pragma unroll
    for (int it = 0; it < 4; ++it) {
        int i    = tid + it * THREADS;       // 0..511 quads
        int code = i >> 2;
        int q    = i & 3;
        uint32_t dst = eqBase + (uint32_t)(code * 64 + ((q ^ ((code >> 2) & 3)) * 16));
        const uint32_t* src = g_eq + (size_t)(chunk * WCHUNK + code) * 16 + q * 4;
        CP16(dst, src);
    }
    CP_COMMIT();
}

__global__ void __launch_bounds__(THREADS, 4)
vq_screen(const float* __restrict__ z, const float* __restrict__ emb,
          float* __restrict__ out)
{
    extern __shared__ char smb[];
    const int tid = threadIdx.x;
    const int tcg = tid & 7;         // code group (4 consecutive codes)
    const int tr  = tid >> 3;        // row group 0..15 (4 rows each)
    const int rowBase = blockIdx.x * ROWS_CTA;

    int*   scnt  = (int*)(smb + SM_CNT);
    int*   senc  = (int*)(smb + SM_ENC);
    int*   scand = (int*)(smb + SM_CAND);
    int*   sidl  = (int*)(smb + SM_IDL);
    float* szz   = (float*)(smb + SM_ZZ);
    float* zf    = (float*)(smb + SM_ZF);

    load_tile(smb, 0, 0, tid);

    // ---- stage z fp32 (stride 68) ----
    const float4* zg = reinterpret_cast<const float4*>(z + (size_t)rowBase * D_DIM);
    #pragma unroll
    for (int it = 0; it < 8; ++it) {
        int q = tid + it * THREADS;          // 0..1023 float4s
        float4 v = zg[q];
        int row = q >> 4, c = (q & 15) << 2;
        *reinterpret_cast<float4*>(&zf[row * 68 + c]) = v;
    }
    __syncthreads();

    // ---- per-row prologue (thread = row, tid<64) ----
    if (tid < ROWS_CTA) {
        const float* zr = &zf[tid * 68];
        float zz = 0.0f, s1 = 0.0f, m = 0.0f;
        #pragma unroll
        for (int d = 0; d < D_DIM; ++d) {
            float v = zr[d];
            zz = __fadd_rn(zz, __fmul_rn(v, v));     // serial exact chain
            s1 += fabsf(v);
            m = fmaxf(m, fabsf(v));
        }
        float sz = 126.0f / fmaxf(m, 1e-30f);
        // pack z int8 swizzled: [row][dg4 ^ ((row>>2)&3)][4 u32]
        int swz = (tid >> 2) & 3;
        #pragma unroll
        for (int g = 0; g < 16; ++g) {
            int dg4 = g >> 2, comp = g & 3;
            uint32_t u = pack4(&zr[g * 4], sz);
            *(uint32_t*)(smb + SM_ZQ + tid * 64 + ((dg4 ^ swz) * 16) + comp * 4) = u;
        }
        szz[tid] = zz;
        // rigorous slack: delta2 = 2*eps_quant + 4*ulp(zz) + ee_max
        float dz   = 0.501f / sz;
        float T1   = dz * 0.015625f;                         // (0.5/sz)*max Sum|e|
        float T2   = (0.501f / S_E) * (s1 + 64.0f * dz);     // (0.5/SE)*Sum|z_hat|
        float eps  = T1 + T2 + 2e-6f;
        float ulpz = __uint_as_float(__float_as_uint(zz * 1.5f + 1e-3f)
                                     & 0x7f800000u) * 1.1920929e-7f;
        float delta2 = 2.0f * eps + 4.0f * ulpz + EEMAX + 1e-6f;
        // u = -(2/(sz*SE))*idot  ->  integer slack
        sidl[tid] = (int)ceilf(delta2 * sz * S_E * 0.5f) + 1;
        scnt[tid] = 0;
        senc[tid] = IBV_INIT;
    }

    load_tile(smb, 1, 1, tid);
    CP_WAIT1();
    __syncthreads();

    // ---- z int8 into registers (chunk-invariant): zq[dg4][r] ----
    const int row0 = tr * 4;
    uint4 zq[4][4];
    {
        const int swzr = tr & 3;                             // (row>>2)&3 for row=4tr+r
        #pragma unroll
        for (int dg4 = 0; dg4 < 4; ++dg4)
            #pragma unroll
            for (int r = 0; r < 4; ++r)
                zq[dg4][r] = *(const uint4*)(smb + SM_ZQ + (row0 + r) * 64
                                             + ((dg4 ^ swzr) * 16));
    }

    int idl[4], ibv[4], ithr[4], pub[4];
    #pragma unroll
    for (int r = 0; r < 4; ++r) {
        idl[r] = sidl[row0 + r];
        ibv[r] = IBV_INIT; ithr[r] = IBV_INIT - idl[r]; pub[r] = IBV_INIT;
    }
    const int eswz = tcg & 3;                                // (code>>2)&3 for code=4tcg+c

    for (int ch = 0; ch < N_CHUNKS; ++ch) {
        const int buf = ch & 1;
        const char* eqB = smb + SM_EQ + buf * 8192;

        // once per chunk: refresh from shared (stale-smaller is safe) + publish
        #pragma unroll
        for (int r = 0; r < 4; ++r) {
            if (ibv[r] > pub[r]) { atomicMax(&senc[row0 + r], ibv[r]); pub[r] = ibv[r]; }
        }
        __syncwarp();
        #pragma unroll
        for (int r = 0; r < 4; ++r) {
            int gbest = senc[row0 + r];
            if (gbest > ibv[r]) ibv[r] = gbest;
            ithr[r] = ibv[r] - idl[r];
        }

        #pragma unroll
        for (int s = 0; s < 4; ++s) {
            const int clBase = s * 32 + tcg * 4;             // local code base
            int acc[4][4];

            // dg4 = 0: dp4a with zero addend
            {
                uint4 eq4[4];
                #pragma unroll
                for (int c = 0; c < 4; ++c)
                    eq4[c] = *(const uint4*)(eqB + (clBase + c) * 64 + (eswz * 16));
                #pragma unroll
                for (int r = 0; r < 4; ++r)
                    #pragma unroll
                    for (int c = 0; c < 4; ++c) {
                        int a;
                        a = __dp4a((int)zq[0][r].x, (int)eq4[c].x, 0);
                        a = __dp4a((int)zq[0][r].y, (int)eq4[c].y, a);
                        a = __dp4a((int)zq[0][r].z, (int)eq4[c].z, a);
                        a = __dp4a((int)zq[0][r].w, (int)eq4[c].w, a);
                        acc[r][c] = a;
                    }
            }
            #pragma unroll
            for (int dg4 = 1; dg4 < 4; ++dg4) {
                uint4 eq4[4];
                #pragma unroll
                for (int c = 0; c < 4; ++c)
                    eq4[c] = *(const uint4*)(eqB + (clBase + c) * 64
                                             + ((dg4 ^ eswz) * 16));
                #pragma unroll
                for (int r = 0; r < 4; ++r)
                    #pragma unroll
                    for (int c = 0; c < 4; ++c) {
                        int a = acc[r][c];
                        a = __dp4a((int)zq[dg4][r].x, (int)eq4[c].x, a);
                        a = __dp4a((int)zq[dg4][r].y, (int)eq4[c].y, a);
                        a = __dp4a((int)zq[dg4][r].z, (int)eq4[c].z, a);
                        a = __dp4a((int)zq[dg4][r].w, (int)eq4[c].w, a);
                        acc[r][c] = a;
                    }
            }

            // integer epilogue: candidate iff idot > ibest - idelta
            const int code0 = ch * WCHUNK + clBase;
            #pragma unroll
            for (int r = 0; r < 4; ++r) {
                #pragma unroll
                for (int c = 0; c < 4; ++c) {
                    int a = acc[r][c];
                    if (a > ithr[r]) {
                        int pos = atomicAdd(&scnt[row0 + r], 1);
                        if (pos < CAP) scand[(row0 + r) * CAP + pos] = code0 + c;
                        if (a > ibv[r]) { ibv[r] = a; ithr[r] = a - idl[r]; }
                    }
                }
            }
        }

        __syncthreads();                                     // done reading buf
        if (ch + 2 < N_CHUNKS) load_tile(smb, buf, ch + 2, tid);
        if (ch + 1 < N_CHUNKS) {
            if (ch + 2 < N_CHUNKS) CP_WAIT1(); else CP_WAIT0();
            __syncthreads();
        }
    }
    __syncthreads();

    // ---- exact rescore (thread = row): serial fma chain, reference rounding ----
    if (tid < ROWS_CTA) {
        const float* zr = &zf[tid * 68];
        const float zz = szz[tid];
        const int myCnt = scnt[tid];
        float bestD = 3.402823466e38f;
        int   bestK = 0;
        if (myCnt <= CAP) {
            for (int i = 0; i < myCnt; ++i) {
                int k = scand[tid * CAP + i];
                const float* eRow = emb + (size_t)k * D_DIM;
                float acc = 0.0f;
                #pragma unroll
                for (int d = 0; d < D_DIM; ++d) {
                    float zv = zr[d];
                    acc = __fmaf_rn(zv + zv, __ldg(&eRow[d]), acc);
                }
                float dd = __fsub_rn(__fadd_rn(zz, __ldg(&g_ee[k])), acc);
                if (dd < bestD || (dd == bestD && k < bestK)) { bestD = dd; bestK = k; }
            }
        } else {
            for (int k = 0; k < K_CODES; ++k) {              // exact fallback
                const float* eRow = emb + (size_t)k * D_DIM;
                float acc = 0.0f;
                #pragma unroll
                for (int d = 0; d < D_DIM; ++d) {
                    float zv = zr[d];
                    acc = __fmaf_rn(zv + zv, __ldg(&eRow[d]), acc);
                }
                float dd = __fsub_rn(__fadd_rn(zz, __ldg(&g_ee[k])), acc);
                if (dd < bestD) { bestD = dd; bestK = k; }
            }
        }

        const int gRow = rowBase + tid;
        out[NQ_ELEMS + gRow] = (float)bestK;

        const float* eRow = emb + (size_t)bestK * D_DIM;
        float* oRow = out + (size_t)gRow * D_DIM;
        double lpart = 0.0;
        #pragma unroll
        for (int d = 0; d < D_DIM; ++d) {
            float q    = __ldg(&eRow[d]);
            float zv   = zr[d];
            float diff = __fsub_rn(q, zv);       // fl(q - z)
            oRow[d]    = __fadd_rn(zv, diff);    // quantized_st = fl(z + fl(q-z))
            lpart += (double)__fmul_rn(diff, diff);
        }
        ((double*)(smb + SM_LOSS))[tid] = lpart;
    }
    __syncthreads();
    if (tid == 0) {
        const double* lb = (const double*)(smb + SM_LOSS);
        double s = 0.0;
        #pragma unroll
        for (int r = 0; r < ROWS_CTA; ++r) s += lb[r];       // fixed order
        g_lossPart[blockIdx.x] = s;
    }
}

// ---------------------------------------------------------------------------
__global__ void vq_finalize(float* __restrict__ out) {
    __shared__ double red[128];
    const int tid = threadIdx.x;
    double s = 0.0;
    #pragma unroll
    for (int i = 0; i < N_BLOCKS / 128; ++i)
        s += g_lossPart[tid * (N_BLOCKS / 128) + i];
    red[tid] = s;
    __syncthreads();
    #pragma unroll
    for (int off = 64; off > 0; off >>= 1) {
        if (tid < off) red[tid] += red[tid + off];
        __syncthreads();
    }
    if (tid == 0) {
        float m = (float)(red[0] / (double)NQ_ELEMS);
        out[NQ_ELEMS + N_ROWS] = __fadd_rn(m, m);            // vq_loss
    }
}

// ---------------------------------------------------------------------------
extern "C" void kernel_launch(void* const* d_in, const int* in_sizes, int n_in,
                              void* d_out, int out_size) {
    const float* z   = (const float*)d_in[0];
    const float* emb = (const float*)d_in[1];
    float* out = (float*)d_out;

    cudaFuncSetAttribute(vq_screen, cudaFuncAttributeMaxDynamicSharedMemorySize,
                         SM_TOTAL);

    vq_prep<<<K_CODES / 32, 256>>>(emb);
    vq_screen<<<N_BLOCKS, THREADS, SM_TOTAL>>>(z, emb, out);
    vq_finalize<<<1, 128>>>(out);
}

// round 12
// speedup vs baseline: 1.1115x; 1.1115x over previous
#include <cuda_runtime.h>
#include <cstdint>

// Problem: B=16, S=4096, D=64, K=4096
#define D_DIM    64
#define K_CODES  4096
#define N_ROWS   65536
#define ROWS_CTA 64
#define THREADS  128
#define WCHUNK   128                    // codes per smem chunk
#define N_CHUNKS (K_CODES / WCHUNK)     // 32
#define N_BLOCKS (N_ROWS / ROWS_CTA)    // 1024
#define NQ_ELEMS (N_ROWS * D_DIM)
#define CAP      64
#define S_E      520192.0f              // 127 * 4096
#define EEMAX    3.8148e-6f             // max ||e||^2 = 64/4096^2 (+margin)
#define IBV_INIT (-(1 << 30))           // safe sentinel: no underflow after -idl

// smem byte offsets
#define SM_EQ    0                      // 2 x 128 x 64  = 16384 (int8 codes, swizzled)
#define SM_ZF    16384                  // 64 x 68 x 4   = 17408 (z fp32)
#define SM_ZQ    33792                  // 64 x 64       = 4096  (z int8, swizzled)
#define SM_CAND  37888                  // 64 x 64 x 4   = 16384
#define SM_CNT   54272                  // 64 x 4
#define SM_ENC   54528                  // 64 x 4 (int running-max idot)
#define SM_ZZ    54784                  // 64 x 4
#define SM_IDL   55040                  // 64 x 4 (int slack)
#define SM_LOSS  55296                  // 64 x 8
#define SM_TOTAL 55808                  // occ 3 (regs are the binding resource)

__device__ uint32_t g_eq[K_CODES * 16];     // packed int8 codebook [k][16 u32]
__device__ float    g_ee[K_CODES];          // exact ||e||^2, serial fp32 chain
__device__ double   g_lossPart[N_BLOCKS];

__device__ __forceinline__ uint32_t smem_u32(const void* p) {
    return (uint32_t)__cvta_generic_to_shared(p);
}
#define CP16(dst, src) \
    asm volatile("cp.async.cg.shared.global [%0], [%1], 16;" :: "r"(dst), "l"(src))
#define CP_COMMIT() asm volatile("cp.async.commit_group;" ::: "memory")
#define CP_WAIT0()  asm volatile("cp.async.wait_group 0;" ::: "memory")
#define CP_WAIT1()  asm volatile("cp.async.wait_group 1;" ::: "memory")

__device__ __forceinline__ uint32_t pack4(const float* v, float s) {
    int a0 = __float2int_rn(v[0] * s), a1 = __float2int_rn(v[1] * s);
    int a2 = __float2int_rn(v[2] * s), a3 = __float2int_rn(v[3] * s);
    return (uint32_t)(a0 & 0xFF) | ((uint32_t)(a1 & 0xFF) << 8) |
           ((uint32_t)(a2 & 0xFF) << 16) | ((uint32_t)(a3 & 0xFF) << 24);
}

// ---------------------------------------------------------------------------
// Prep: exact ||e||^2 (serial fp32) + packed int8 codebook
// ---------------------------------------------------------------------------
__global__ void vq_prep(const float* __restrict__ emb) {
    __shared__ float tile[32][D_DIM + 1];
    const int tid = threadIdx.x;             // 256
    const int k0  = blockIdx.x * 32;

    #pragma unroll
    for (int it = 0; it < 8; ++it) {
        int i = tid + it * 256;
        int kl = i >> 6, d = i & 63;
        tile[kl][d] = __ldg(&emb[(size_t)(k0 + kl) * D_DIM + d]);
    }
    __syncthreads();

    if (tid < 32) {
        float s = 0.0f;
        #pragma unroll
        for (int d = 0; d < D_DIM; ++d) {
            float v = tile[tid][d];
            s = __fadd_rn(s, __fmul_rn(v, v));
        }
        g_ee[k0 + tid] = s;
    }
    #pragma unroll
    for (int it = 0; it < 2; ++it) {
        int i = tid + it * 256;              // 0..511
        int code = i >> 4, g = i & 15;
        g_eq[(size_t)(k0 + code) * 16 + g] = pack4(&tile[code][g * 4], S_E);
    }
}

// ---------------------------------------------------------------------------
// Screen (integer) + exact rescore
// ---------------------------------------------------------------------------
__device__ __forceinline__ void load_tile(char* smb, int buf, int chunk, int tid) {
    uint32_t eqBase = smem_u32(smb + SM_EQ + buf * 8192);
    #pragma unroll
    for (int it = 0; it < 4; ++it) {
        int i    = tid + it * THREADS;       // 0..511 quads
        int code = i >> 2;
        int q    = i & 3;
        uint32_t dst = eqBase + (uint32_t)(code * 64 + ((q ^ ((code >> 2) & 3)) * 16));
        const uint32_t* src = g_eq + (size_t)(chunk * WCHUNK + code) * 16 + q * 4;
        CP16(dst, src);
    }
    CP_COMMIT();
}

__global__ void __launch_bounds__(THREADS, 3)
vq_screen(const float* __restrict__ z, const float* __restrict__ emb,
          float* __restrict__ out)
{
    extern __shared__ char smb[];
    const int tid = threadIdx.x;
    const int tcg = tid & 7;         // code group (4 consecutive codes)
    const int tr  = tid >> 3;        // row group 0..15 (4 rows each)
    const int rowBase = blockIdx.x * ROWS_CTA;

    int*   scnt  = (int*)(smb + SM_CNT);
    int*   senc  = (int*)(smb + SM_ENC);
    int*   scand = (int*)(smb + SM_CAND);
    int*   sidl  = (int*)(smb + SM_IDL);
    float* szz   = (float*)(smb + SM_ZZ);
    float* zf    = (float*)(smb + SM_ZF);

    load_tile(smb, 0, 0, tid);

    // ---- stage z fp32 (stride 68) ----
    const float4* zg = reinterpret_cast<const float4*>(z + (size_t)rowBase * D_DIM);
    #pragma unroll
    for (int it = 0; it < 8; ++it) {
        int q = tid + it * THREADS;          // 0..1023 float4s
        float4 v = zg[q];
        int row = q >> 4, c = (q & 15) << 2;
        *reinterpret_cast<float4*>(&zf[row * 68 + c]) = v;
    }
    __syncthreads();

    // ---- per-row prologue (thread = row, tid<64) ----
    if (tid < ROWS_CTA) {
        const float* zr = &zf[tid * 68];
        float zz = 0.0f, s1 = 0.0f, m = 0.0f;
        #pragma unroll
        for (int d = 0; d < D_DIM; ++d) {
            float v = zr[d];
            zz = __fadd_rn(zz, __fmul_rn(v, v));     // serial exact chain
            s1 += fabsf(v);
            m = fmaxf(m, fabsf(v));
        }
        float sz = 126.0f / fmaxf(m, 1e-30f);
        // pack z int8 swizzled: [row][dg4 ^ ((row>>2)&3)][4 u32]
        int swz = (tid >> 2) & 3;
        #pragma unroll
        for (int g = 0; g < 16; ++g) {
            int dg4 = g >> 2, comp = g & 3;
            uint32_t u = pack4(&zr[g * 4], sz);
            *(uint32_t*)(smb + SM_ZQ + tid * 64 + ((dg4 ^ swz) * 16) + comp * 4) = u;
        }
        szz[tid] = zz;
        // rigorous slack: delta2 = 2*eps_quant + 4*ulp(zz) + ee_max
        float dz   = 0.501f / sz;
        float T1   = dz * 0.015625f;                         // (0.5/sz)*max Sum|e|
        float T2   = (0.501f / S_E) * (s1 + 64.0f * dz);     // (0.5/SE)*Sum|z_hat|
        float eps  = T1 + T2 + 2e-6f;
        float ulpz = __uint_as_float(__float_as_uint(zz * 1.5f + 1e-3f)
                                     & 0x7f800000u) * 1.1920929e-7f;
        float delta2 = 2.0f * eps + 4.0f * ulpz + EEMAX + 1e-6f;
        // u = -(2/(sz*SE))*idot  ->  integer slack
        sidl[tid] = (int)ceilf(delta2 * sz * S_E * 0.5f) + 1;
        scnt[tid] = 0;
        senc[tid] = IBV_INIT;
    }

    load_tile(smb, 1, 1, tid);
    CP_WAIT1();
    __syncthreads();

    // ---- z int8 into registers (chunk-invariant): zq[dg4][r] ----
    const int row0 = tr * 4;
    uint4 zq[4][4];
    {
        const int swzr = tr & 3;                             // (row>>2)&3 for row=4tr+r
        #pragma unroll
        for (int dg4 = 0; dg4 < 4; ++dg4)
            #pragma unroll
            for (int r = 0; r < 4; ++r)
                zq[dg4][r] = *(const uint4*)(smb + SM_ZQ + (row0 + r) * 64
                                             + ((dg4 ^ swzr) * 16));
    }

    int idl[4], ibv[4], ithr[4], pub[4];
    #pragma unroll
    for (int r = 0; r < 4; ++r) {
        idl[r] = sidl[row0 + r];
        ibv[r] = IBV_INIT; ithr[r] = IBV_INIT - idl[r]; pub[r] = IBV_INIT;
    }
    const int eswz = tcg & 3;                                // (code>>2)&3 for code=4tcg+c

    for (int ch = 0; ch < N_CHUNKS; ++ch) {
        const int buf = ch & 1;
        const char* eqB = smb + SM_EQ + buf * 8192;

        // once per chunk: publish + refresh from shared (stale-smaller is safe)
        #pragma unroll
        for (int r = 0; r < 4; ++r) {
            if (ibv[r] > pub[r]) { atomicMax(&senc[row0 + r], ibv[r]); pub[r] = ibv[r]; }
        }
        __syncwarp();
        #pragma unroll
        for (int r = 0; r < 4; ++r) {
            int gbest = senc[row0 + r];
            if (gbest > ibv[r]) ibv[r] = gbest;
            ithr[r] = ibv[r] - idl[r];
        }

        #pragma unroll
        for (int s = 0; s < 4; ++s) {
            const int clBase = s * 32 + tcg * 4;             // local code base
            int acc[4][4];

            // dg4 = 0: dp4a with zero addend
            {
                uint4 eq4[4];
                #pragma unroll
                for (int c = 0; c < 4; ++c)
                    eq4[c] = *(const uint4*)(eqB + (clBase + c) * 64 + (eswz * 16));
                #pragma unroll
                for (int r = 0; r < 4; ++r)
                    #pragma unroll
                    for (int c = 0; c < 4; ++c) {
                        int a;
                        a = __dp4a((int)zq[0][r].x, (int)eq4[c].x, 0);
                        a = __dp4a((int)zq[0][r].y, (int)eq4[c].y, a);
                        a = __dp4a((int)zq[0][r].z, (int)eq4[c].z, a);
                        a = __dp4a((int)zq[0][r].w, (int)eq4[c].w, a);
                        acc[r][c] = a;
                    }
            }
            #pragma unroll
            for (int dg4 = 1; dg4 < 4; ++dg4) {
                uint4 eq4[4];
                #pragma unroll
                for (int c = 0; c < 4; ++c)
                    eq4[c] = *(const uint4*)(eqB + (clBase + c) * 64
                                             + ((dg4 ^ eswz) * 16));
                #pragma unroll
                for (int r = 0; r < 4; ++r)
                    #pragma unroll
                    for (int c = 0; c < 4; ++c) {
                        int a = acc[r][c];
                        a = __dp4a((int)zq[dg4][r].x, (int)eq4[c].x, a);
                        a = __dp4a((int)zq[dg4][r].y, (int)eq4[c].y, a);
                        a = __dp4a((int)zq[dg4][r].z, (int)eq4[c].z, a);
                        a = __dp4a((int)zq[dg4][r].w, (int)eq4[c].w, a);
                        acc[r][c] = a;
                    }
            }

            // integer epilogue: candidate iff idot > ibest - idelta
            const int code0 = ch * WCHUNK + clBase;
            #pragma unroll
            for (int r = 0; r < 4; ++r) {
                #pragma unroll
                for (int c = 0; c < 4; ++c) {
                    int a = acc[r][c];
                    if (a > ithr[r]) {
                        int pos = atomicAdd(&scnt[row0 + r], 1);
                        if (pos < CAP) scand[(row0 + r) * CAP + pos] = code0 + c;
                        if (a > ibv[r]) { ibv[r] = a; ithr[r] = a - idl[r]; }
                    }
                }
            }
        }

        __syncthreads();                                     // done reading buf
        if (ch + 2 < N_CHUNKS) load_tile(smb, buf, ch + 2, tid);
        if (ch + 1 < N_CHUNKS) {
            if (ch + 2 < N_CHUNKS) CP_WAIT1(); else CP_WAIT0();
            __syncthreads();
        }
    }
    __syncthreads();

    // ---- exact rescore (thread = row): serial fma chain, reference rounding ----
    if (tid < ROWS_CTA) {
        const float* zr = &zf[tid * 68];
        const float zz = szz[tid];
        const int myCnt = scnt[tid];
        float bestD = 3.402823466e38f;
        int   bestK = 0;
        if (myCnt <= CAP) {
            for (int i = 0; i < myCnt; ++i) {
                int k = scand[tid * CAP + i];
                const float* eRow = emb + (size_t)k * D_DIM;
                float acc = 0.0f;
                #pragma unroll
                for (int d = 0; d < D_DIM; ++d) {
                    float zv = zr[d];
                    acc = __fmaf_rn(zv + zv, __ldg(&eRow[d]), acc);
                }
                float dd = __fsub_rn(__fadd_rn(zz, __ldg(&g_ee[k])), acc);
                if (dd < bestD || (dd == bestD && k < bestK)) { bestD = dd; bestK = k; }
            }
        } else {
            for (int k = 0; k < K_CODES; ++k) {              // exact fallback
                const float* eRow = emb + (size_t)k * D_DIM;
                float acc = 0.0f;
                #pragma unroll
                for (int d = 0; d < D_DIM; ++d) {
                    float zv = zr[d];
                    acc = __fmaf_rn(zv + zv, __ldg(&eRow[d]), acc);
                }
                float dd = __fsub_rn(__fadd_rn(zz, __ldg(&g_ee[k])), acc);
                if (dd < bestD) { bestD = dd; bestK = k; }
            }
        }

        const int gRow = rowBase + tid;
        out[NQ_ELEMS + gRow] = (float)bestK;

        const float* eRow = emb + (size_t)bestK * D_DIM;
        float* oRow = out + (size_t)gRow * D_DIM;
        double lpart = 0.0;
        #pragma unroll
        for (int d = 0; d < D_DIM; ++d) {
            float q    = __ldg(&eRow[d]);
            float zv   = zr[d];
            float diff = __fsub_rn(q, zv);       // fl(q - z)
            oRow[d]    = __fadd_rn(zv, diff);    // quantized_st = fl(z + fl(q-z))
            lpart += (double)__fmul_rn(diff, diff);
        }
        ((double*)(smb + SM_LOSS))[tid] = lpart;
    }
    __syncthreads();
    if (tid == 0) {
        const double* lb = (const double*)(smb + SM_LOSS);
        double s = 0.0;
        #pragma unroll
        for (int r = 0; r < ROWS_CTA; ++r) s += lb[r];       // fixed order
        g_lossPart[blockIdx.x] = s;
    }
}

// ---------------------------------------------------------------------------
__global__ void vq_finalize(float* __restrict__ out) {
    __shared__ double red[128];
    const int tid = threadIdx.x;
    double s = 0.0;
    #pragma unroll
    for (int i = 0; i < N_BLOCKS / 128; ++i)
        s += g_lossPart[tid * (N_BLOCKS / 128) + i];
    red[tid] = s;
    __syncthreads();
    #pragma unroll
    for (int off = 64; off > 0; off >>= 1) {
        if (tid < off) red[tid] += red[tid + off];
        __syncthreads();
    }
    if (tid == 0) {
        float m = (float)(red[0] / (double)NQ_ELEMS);
        out[NQ_ELEMS + N_ROWS] = __fadd_rn(m, m);            // vq_loss
    }
}

// ---------------------------------------------------------------------------
extern "C" void kernel_launch(void* const* d_in, const int* in_sizes, int n_in,
                              void* d_out, int out_size) {
    const float* z   = (const float*)d_in[0];
    const float* emb = (const float*)d_in[1];
    float* out = (float*)d_out;

    cudaFuncSetAttribute(vq_screen, cudaFuncAttributeMaxDynamicSharedMemorySize,
                         SM_TOTAL);

    vq_prep<<<K_CODES / 32, 256>>>(emb);
    vq_screen<<<N_BLOCKS, THREADS, SM_TOTAL>>>(z, emb, out);
    vq_finalize<<<1, 128>>>(out);
}

// round 13
// speedup vs baseline: 4.2309x; 3.8066x over previous
#include <cuda_runtime.h>
#include <cstdint>

// Problem: B=16, S=4096, D=64, K=4096
#define D_DIM    64
#define K_CODES  4096
#define N_ROWS   65536
#define ROWS_CTA 64
#define THREADS  128
#define WCHUNK   128                    // codes per smem chunk
#define N_CHUNKS (K_CODES / WCHUNK)     // 32
#define N_BLOCKS (N_ROWS / ROWS_CTA)    // 1024
#define NQ_ELEMS (N_ROWS * D_DIM)
#define CAP      96
#define S_E      520192.0f              // 127 * 4096
#define EEMAX    3.8148e-6f             // max ||e||^2 = 64/4096^2 (+margin)
#define IBV_INIT (-(1 << 30))           // safe sentinel: no underflow after -idl

// smem byte offsets (triple-buffered EQ)
#define SM_EQ    0                      // 3 x 128 x 64  = 24576 (int8 codes, swizzled)
#define SM_ZF    24576                  // 64 x 68 x 4   = 17408 (z fp32)
#define SM_ZQ    41984                  // 64 x 64       = 4096  (z int8, swizzled)
#define SM_CAND  46080                  // 64 x 96 x 4   = 24576
#define SM_CNT   70656                  // 64 x 4
#define SM_ENC   70912                  // 64 x 4 (int running-max idot)
#define SM_ZZ    71168                  // 64 x 4
#define SM_IDL   71424                  // 64 x 4 (int slack)
#define SM_LOSS  71680                  // 64 x 8
#define SM_TOTAL 72192                  // x3 = 216576 <= 227KB -> occ 3

__device__ uint32_t g_eq[K_CODES * 16];     // packed int8 codebook [k][16 u32]
__device__ float    g_ee[K_CODES];          // exact ||e||^2, serial fp32 chain
__device__ double   g_lossPart[N_BLOCKS];

__device__ __forceinline__ uint32_t smem_u32(const void* p) {
    return (uint32_t)__cvta_generic_to_shared(p);
}
#define CP16(dst, src) \
    asm volatile("cp.async.cg.shared.global [%0], [%1], 16;" :: "r"(dst), "l"(src))
#define CP_COMMIT() asm volatile("cp.async.commit_group;" ::: "memory")
#define CP_WAIT0()  asm volatile("cp.async.wait_group 0;" ::: "memory")
#define CP_WAIT1()  asm volatile("cp.async.wait_group 1;" ::: "memory")

__device__ __forceinline__ uint32_t pack4(const float* v, float s) {
    int a0 = __float2int_rn(v[0] * s), a1 = __float2int_rn(v[1] * s);
    int a2 = __float2int_rn(v[2] * s), a3 = __float2int_rn(v[3] * s);
    return (uint32_t)(a0 & 0xFF) | ((uint32_t)(a1 & 0xFF) << 8) |
           ((uint32_t)(a2 & 0xFF) << 16) | ((uint32_t)(a3 & 0xFF) << 24);
}

// ---------------------------------------------------------------------------
// Prep: exact ||e||^2 (serial fp32) + packed int8 codebook
// ---------------------------------------------------------------------------
__global__ void vq_prep(const float* __restrict__ emb) {
    __shared__ float tile[32][D_DIM + 1];
    const int tid = threadIdx.x;             // 256
    const int k0  = blockIdx.x * 32;

    #pragma unroll
    for (int it = 0; it < 8; ++it) {
        int i = tid + it * 256;
        int kl = i >> 6, d = i & 63;
        tile[kl][d] = __ldg(&emb[(size_t)(k0 + kl) * D_DIM + d]);
    }
    __syncthreads();

    if (tid < 32) {
        float s = 0.0f;
        #pragma unroll
        for (int d = 0; d < D_DIM; ++d) {
            float v = tile[tid][d];
            s = __fadd_rn(s, __fmul_rn(v, v));
        }
        g_ee[k0 + tid] = s;
    }
    #pragma unroll
    for (int it = 0; it < 2; ++it) {
        int i = tid + it * 256;              // 0..511
        int code = i >> 4, g = i & 15;
        g_eq[(size_t)(k0 + code) * 16 + g] = pack4(&tile[code][g * 4], S_E);
    }
}

// ---------------------------------------------------------------------------
// Screen (integer) + exact rescore
// ---------------------------------------------------------------------------
__device__ __forceinline__ void load_tile(char* smb, int buf, int chunk, int tid) {
    uint32_t eqBase = smem_u32(smb + SM_EQ + buf * 8192);
    #pragma unroll
    for (int it = 0; it < 4; ++it) {
        int i    = tid + it * THREADS;       // 0..511 quads
        int code = i >> 2;
        int q    = i & 3;
        uint32_t dst = eqBase + (uint32_t)(code * 64 + ((q ^ ((code >> 2) & 3)) * 16));
        const uint32_t* src = g_eq + (size_t)(chunk * WCHUNK + code) * 16 + q * 4;
        CP16(dst, src);
    }
    CP_COMMIT();
}

__global__ void __launch_bounds__(THREADS, 3)
vq_screen(const float* __restrict__ z, const float* __restrict__ emb,
          float* __restrict__ out)
{
    extern __shared__ char smb[];
    const int tid = threadIdx.x;
    const int tcg = tid & 7;         // code group (4 consecutive codes)
    const int tr  = tid >> 3;        // row group 0..15 (4 rows each)
    const int rowBase = blockIdx.x * ROWS_CTA;

    int*   scnt  = (int*)(smb + SM_CNT);
    int*   senc  = (int*)(smb + SM_ENC);
    int*   scand = (int*)(smb + SM_CAND);
    int*   sidl  = (int*)(smb + SM_IDL);
    float* szz   = (float*)(smb + SM_ZZ);
    float* zf    = (float*)(smb + SM_ZF);

    load_tile(smb, 0, 0, tid);

    // ---- stage z fp32 (stride 68) ----
    const float4* zg = reinterpret_cast<const float4*>(z + (size_t)rowBase * D_DIM);
    #pragma unroll
    for (int it = 0; it < 8; ++it) {
        int q = tid + it * THREADS;          // 0..1023 float4s
        float4 v = zg[q];
        int row = q >> 4, c = (q & 15) << 2;
        *reinterpret_cast<float4*>(&zf[row * 68 + c]) = v;
    }
    __syncthreads();

    // ---- per-row prologue (thread = row, tid<64) ----
    if (tid < ROWS_CTA) {
        const float* zr = &zf[tid * 68];
        float zz = 0.0f, s1 = 0.0f, m = 0.0f;
        #pragma unroll
        for (int d = 0; d < D_DIM; ++d) {
            float v = zr[d];
            zz = __fadd_rn(zz, __fmul_rn(v, v));     // serial exact chain
            s1 += fabsf(v);
            m = fmaxf(m, fabsf(v));
        }
        float sz = 126.0f / fmaxf(m, 1e-30f);
        // pack z int8 swizzled: [row][dg4 ^ ((row>>2)&3)][4 u32]
        int swz = (tid >> 2) & 3;
        #pragma unroll
        for (int g = 0; g < 16; ++g) {
            int dg4 = g >> 2, comp = g & 3;
            uint32_t u = pack4(&zr[g * 4], sz);
            *(uint32_t*)(smb + SM_ZQ + tid * 64 + ((dg4 ^ swz) * 16) + comp * 4) = u;
        }
        szz[tid] = zz;
        // rigorous slack: delta2 = 2*eps_quant + 4*ulp(zz) + ee_max
        float dz   = 0.501f / sz;
        float T1   = dz * 0.015625f;                         // (0.5/sz)*max Sum|e|
        float T2   = (0.501f / S_E) * (s1 + 64.0f * dz);     // (0.5/SE)*Sum|z_hat|
        float eps  = T1 + T2 + 2e-6f;
        float ulpz = __uint_as_float(__float_as_uint(zz * 1.5f + 1e-3f)
                                     & 0x7f800000u) * 1.1920929e-7f;
        float delta2 = 2.0f * eps + 4.0f * ulpz + EEMAX + 1e-6f;
        // u = -(2/(sz*SE))*idot  ->  integer slack
        sidl[tid] = (int)ceilf(delta2 * sz * S_E * 0.5f) + 1;
        scnt[tid] = 0;
        senc[tid] = IBV_INIT;
    }

    load_tile(smb, 1, 1, tid);
    CP_WAIT1();                              // chunk 0 landed
    __syncthreads();

    // ---- z int8 into registers (chunk-invariant): zq[dg4][r] ----
    const int row0 = tr * 4;
    uint4 zq[4][4];
    {
        const int swzr = tr & 3;                             // (row>>2)&3 for row=4tr+r
        #pragma unroll
        for (int dg4 = 0; dg4 < 4; ++dg4)
            #pragma unroll
            for (int r = 0; r < 4; ++r)
                zq[dg4][r] = *(const uint4*)(smb + SM_ZQ + (row0 + r) * 64
                                             + ((dg4 ^ swzr) * 16));
    }

    int idl[4], ibv[4], ithr[4], pub[4];
    #pragma unroll
    for (int r = 0; r < 4; ++r) {
        idl[r] = sidl[row0 + r];
        ibv[r] = IBV_INIT; ithr[r] = IBV_INIT - idl[r]; pub[r] = IBV_INIT;
    }
    const int eswz = tcg & 3;                                // (code>>2)&3 for code=4tcg+c

    for (int ch = 0; ch < N_CHUNKS; ++ch) {
        const char* eqB = smb + SM_EQ + (ch % 3) * 8192;

        #pragma unroll
        for (int s = 0; s < 4; ++s) {
            // per-s-step refresh from shared (stale-smaller is safe) — R10 cadence
            #pragma unroll
            for (int r = 0; r < 4; ++r) {
                int gbest = senc[row0 + r];
                if (gbest > ibv[r]) ibv[r] = gbest;
                ithr[r] = ibv[r] - idl[r];
            }

            const int clBase = s * 32 + tcg * 4;             // local code base
            int acc[4][4];

            // dg4 = 0: dp4a with zero addend
            {
                uint4 eq4[4];
                #pragma unroll
                for (int c = 0; c < 4; ++c)
                    eq4[c] = *(const uint4*)(eqB + (clBase + c) * 64 + (eswz * 16));
                #pragma unroll
                for (int r = 0; r < 4; ++r)
                    #pragma unroll
                    for (int c = 0; c < 4; ++c) {
                        int a;
                        a = __dp4a((int)zq[0][r].x, (int)eq4[c].x, 0);
                        a = __dp4a((int)zq[0][r].y, (int)eq4[c].y, a);
                        a = __dp4a((int)zq[0][r].z, (int)eq4[c].z, a);
                        a = __dp4a((int)zq[0][r].w, (int)eq4[c].w, a);
                        acc[r][c] = a;
                    }
            }
            #pragma unroll
            for (int dg4 = 1; dg4 < 4; ++dg4) {
                uint4 eq4[4];
                #pragma unroll
                for (int c = 0; c < 4; ++c)
                    eq4[c] = *(const uint4*)(eqB + (clBase + c) * 64
                                             + ((dg4 ^ eswz) * 16));
                #pragma unroll
                for (int r = 0; r < 4; ++r)
                    #pragma unroll
                    for (int c = 0; c < 4; ++c) {
                        int a = acc[r][c];
                        a = __dp4a((int)zq[dg4][r].x, (int)eq4[c].x, a);
                        a = __dp4a((int)zq[dg4][r].y, (int)eq4[c].y, a);
                        a = __dp4a((int)zq[dg4][r].z, (int)eq4[c].z, a);
                        a = __dp4a((int)zq[dg4][r].w, (int)eq4[c].w, a);
                        acc[r][c] = a;
                    }
            }

            // integer epilogue: candidate iff idot > ibest - idelta
            const int code0 = ch * WCHUNK + clBase;
            #pragma unroll
            for (int r = 0; r < 4; ++r) {
                #pragma unroll
                for (int c = 0; c < 4; ++c) {
                    int a = acc[r][c];
                    if (a > ithr[r]) {
                        int pos = atomicAdd(&scnt[row0 + r], 1);
                        if (pos < CAP) scand[(row0 + r) * CAP + pos] = code0 + c;
                        if (a > ibv[r]) { ibv[r] = a; ithr[r] = a - idl[r]; }
                    }
                }
            }
            // publish improvements (R10 cadence: per s-step)
            #pragma unroll
            for (int r = 0; r < 4; ++r)
                if (ibv[r] > pub[r]) {
                    atomicMax(&senc[row0 + r], ibv[r]);
                    pub[r] = ibv[r];
                }
        }

        // triple-buffered: single barrier per chunk
        if (ch + 2 < N_CHUNKS) load_tile(smb, (ch + 2) % 3, ch + 2, tid);
        if (ch + 1 < N_CHUNKS) {
            if (ch + 2 < N_CHUNKS) CP_WAIT1(); else CP_WAIT0();
        }
        __syncthreads();
    }

    // ---- exact rescore (thread = row): serial fma chain, reference rounding ----
    if (tid < ROWS_CTA) {
        const float* zr = &zf[tid * 68];
        const float zz = szz[tid];
        const int myCnt = scnt[tid];
        float bestD = 3.402823466e38f;
        int   bestK = 0;
        if (myCnt <= CAP) {
            for (int i = 0; i < myCnt; ++i) {
                int k = scand[tid * CAP + i];
                const float* eRow = emb + (size_t)k * D_DIM;
                float acc = 0.0f;
                #pragma unroll
                for (int d = 0; d < D_DIM; ++d) {
                    float zv = zr[d];
                    acc = __fmaf_rn(zv + zv, __ldg(&eRow[d]), acc);
                }
                float dd = __fsub_rn(__fadd_rn(zz, __ldg(&g_ee[k])), acc);
                if (dd < bestD || (dd == bestD && k < bestK)) { bestD = dd; bestK = k; }
            }
        } else {
            for (int k = 0; k < K_CODES; ++k) {              // exact fallback
                const float* eRow = emb + (size_t)k * D_DIM;
                float acc = 0.0f;
                #pragma unroll
                for (int d = 0; d < D_DIM; ++d) {
                    float zv = zr[d];
                    acc = __fmaf_rn(zv + zv, __ldg(&eRow[d]), acc);
                }
                float dd = __fsub_rn(__fadd_rn(zz, __ldg(&g_ee[k])), acc);
                if (dd < bestD) { bestD = dd; bestK = k; }
            }
        }

        const int gRow = rowBase + tid;
        out[NQ_ELEMS + gRow] = (float)bestK;

        const float* eRow = emb + (size_t)bestK * D_DIM;
        float* oRow = out + (size_t)gRow * D_DIM;
        double lpart = 0.0;
        #pragma unroll
        for (int d = 0; d < D_DIM; ++d) {
            float q    = __ldg(&eRow[d]);
            float zv   = zr[d];
            float diff = __fsub_rn(q, zv);       // fl(q - z)
            oRow[d]    = __fadd_rn(zv, diff);    // quantized_st = fl(z + fl(q-z))
            lpart += (double)__fmul_rn(diff, diff);
        }
        ((double*)(smb + SM_LOSS))[tid] = lpart;
    }
    __syncthreads();
    if (tid == 0) {
        const double* lb = (const double*)(smb + SM_LOSS);
        double s = 0.0;
        #pragma unroll
        for (int r = 0; r < ROWS_CTA; ++r) s += lb[r];       // fixed order
        g_lossPart[blockIdx.x] = s;
    }
}

// ---------------------------------------------------------------------------
__global__ void vq_finalize(float* __restrict__ out) {
    __shared__ double red[128];
    const int tid = threadIdx.x;
    double s = 0.0;
    #pragma unroll
    for (int i = 0; i < N_BLOCKS / 128; ++i)
        s += g_lossPart[tid * (N_BLOCKS / 128) + i];
    red[tid] = s;
    __syncthreads();
    #pragma unroll
    for (int off = 64; off > 0; off >>= 1) {
        if (tid < off) red[tid] += red[tid + off];
        __syncthreads();
    }
    if (tid == 0) {
        float m = (float)(red[0] / (double)NQ_ELEMS);
        out[NQ_ELEMS + N_ROWS] = __fadd_rn(m, m);            // vq_loss
    }
}

// ---------------------------------------------------------------------------
extern "C" void kernel_launch(void* const* d_in, const int* in_sizes, int n_in,
                              void* d_out, int out_size) {
    const float* z   = (const float*)d_in[0];
    const float* emb = (const float*)d_in[1];
    float* out = (float*)d_out;

    cudaFuncSetAttribute(vq_screen, cudaFuncAttributeMaxDynamicSharedMemorySize,
                         SM_TOTAL);

    vq_prep<<<K_CODES / 32, 256>>>(emb);
    vq_screen<<<N_BLOCKS, THREADS, SM_TOTAL>>>(z, emb, out);
    vq_finalize<<<1, 128>>>(out);
}